// round 17
// baseline (speedup 1.0000x reference)
#include <cuda_runtime.h>
#include <cuda_fp16.h>
#include <mma.h>
#include <cstddef>

#define HEADS  8
#define NNODES 8192
#define NEDGES 131072
#define NEG    0.2f
#define CAP    128          // bucket capacity per dst (max degree ~40 for Binomial(131072,1/8192))

typedef unsigned long long ull;
using namespace nvcuda;

// ---------------- scratch (static __device__, zero-initialized) -------------
__device__ __half g_h1lin_h[NNODES*64];             // fp16 interchange (1MB)
__device__ float  g_as1[NNODES*HEADS];
__device__ float  g_ad1[NNODES*HEADS];
__device__ __half g_h1h[NNODES*64];                 // fp16 h1 (wmma A operand)
__device__ __half g_W2h[64*1024];                   // fp16 W2 (wmma B operand)
__device__ __half g_h2lin_h[(size_t)NNODES*1024];  // 16MB fp16 interchange
__device__ __half g_h2h[(size_t)NNODES*1024];      // 16MB fp16 interchange
__device__ float  g_as2[NNODES*HEADS];
__device__ float  g_ad2[NNODES*HEADS];
__device__ int    g_deg[NNODES];                    // zero at entry; re-zeroed by final
__device__ int    g_srcs[NNODES*CAP];               // 4MB bucket array
__device__ int    g_is64;
__device__ float  g_Ms[64*8];
__device__ float  g_Md[64*8];
__device__ float  g_M1s[16*8];
__device__ float  g_M1d[16*8];
__device__ float  g_valacc[512];                    // zero at entry; re-zeroed by final
__device__ float  g_advacc[128];

struct h4 { __half2 a, b; };
struct __align__(16) h8 { __half2 a, b, c, d; };

__device__ __forceinline__ float lrelu(float x){ return x > 0.f ? x : NEG*x; }

__device__ __forceinline__ void shfl_add(float4& v, int off){
    v.x += __shfl_down_sync(~0u, v.x, off);
    v.y += __shfl_down_sync(~0u, v.y, off);
    v.z += __shfl_down_sync(~0u, v.z, off);
    v.w += __shfl_down_sync(~0u, v.w, off);
}

// ---- packed fp32x2 helpers (Blackwell) ----
__device__ __forceinline__ ull pack2(float lo, float hi){
    ull r;
    asm("mov.b64 %0, {%1, %2};" : "=l"(r) : "r"(__float_as_uint(lo)), "r"(__float_as_uint(hi)));
    return r;
}
__device__ __forceinline__ void unpack2(ull v, float& lo, float& hi){
    unsigned int a, b;
    asm("mov.b64 {%0, %1}, %2;" : "=r"(a), "=r"(b) : "l"(v));
    lo = __uint_as_float(a); hi = __uint_as_float(b);
}
__device__ __forceinline__ void fma2(ull& d, ull a, ull b){
    asm("fma.rn.f32x2 %0, %1, %2, %0;" : "+l"(d) : "l"(a), "l"(b));
}

// prep: blocks 0..63 = M(W2@a2); 64 = sniff; 65 = M1; 66..73 = W2->fp16 -----
__global__ __launch_bounds__(512) void prep_kernel(const int* __restrict__ e32,
                                                   const float* __restrict__ W1,
                                                   const float* __restrict__ a_s1,
                                                   const float* __restrict__ a_d1,
                                                   const float* __restrict__ W2,
                                                   const float* __restrict__ a_s2,
                                                   const float* __restrict__ a_d2){
    int t = threadIdx.x;
    int bk = blockIdx.x;
    if (bk >= 66){
        int base = (bk - 66)*8192;
#pragma unroll
        for (int q = 0; q < 16; q++){
            int i = base + q*512 + t;
            g_W2h[i] = __float2half(W2[i]);
        }
        return;
    }
    if (bk == 64){
        __shared__ int nz;
        if (t == 0) nz = 0;
        __syncthreads();
        int v = 0;
        for (int i = t; i < 8192; i += 512) v |= e32[2*i+1];
        if (v) atomicOr(&nz, 1);
        __syncthreads();
        if (t == 0) g_is64 = (nz == 0) ? 1 : 0;
        return;
    }
    if (bk == 65){
        if (t < 128){
            int k = t >> 3, h = t & 7;
            float ms = 0.f, md = 0.f;
#pragma unroll
            for (int c = 0; c < 8; c++){
                float wv = W1[k*64 + h*8 + c];
                ms += wv * a_s1[h*8 + c];
                md += wv * a_d1[h*8 + c];
            }
            g_M1s[k*8 + h] = ms;
            g_M1d[k*8 + h] = md;
        }
        return;
    }
    int k = bk;   // 0..63
    __shared__ float sm[16][4];
    float w1  = W2[k*1024 + t];
    float w2v = W2[k*1024 + 512 + t];
    float p1s = w1  * a_s2[t];
    float p1d = w1  * a_d2[t];
    float p2s = w2v * a_s2[512 + t];
    float p2d = w2v * a_d2[512 + t];
#pragma unroll
    for (int off = 16; off; off >>= 1){
        p1s += __shfl_down_sync(~0u, p1s, off);
        p1d += __shfl_down_sync(~0u, p1d, off);
        p2s += __shfl_down_sync(~0u, p2s, off);
        p2d += __shfl_down_sync(~0u, p2d, off);
    }
    int w = t >> 5, l = t & 31;
    if (l == 0){ sm[w][0]=p1s; sm[w][1]=p1d; sm[w][2]=p2s; sm[w][3]=p2d; }
    __syncthreads();
    if (t < 8){
        float ms, md;
        if (t < 4){
            int b = t*4;
            ms = sm[b][0]+sm[b+1][0]+sm[b+2][0]+sm[b+3][0];
            md = sm[b][1]+sm[b+1][1]+sm[b+2][1]+sm[b+3][1];
        } else {
            int b = (t-4)*4;
            ms = sm[b][2]+sm[b+1][2]+sm[b+2][2]+sm[b+3][2];
            md = sm[b][3]+sm[b+1][3]+sm[b+2][3]+sm[b+3][3];
        }
        g_Ms[k*8 + t] = ms;
        g_Md[k*8 + t] = md;
    }
}

// ---------------- bucket scatter: one-pass CSR (count+place) ----------------
__global__ void scatter_kernel(const void* edge){
    int e = blockIdx.x*256 + threadIdx.x;
    if (e >= NEDGES) return;
    int s, d;
    if (g_is64){
        s = (int)((const long long*)edge)[e];
        d = (int)((const long long*)edge)[NEDGES + e];
    } else {
        s = ((const int*)edge)[e];
        d = ((const int*)edge)[NEDGES + e];
    }
    int pos = atomicAdd(&g_deg[d], 1);
    g_srcs[d*CAP + pos] = s;
}

// ------- layer 1 linear + logits via M1 (no shuffles; 4 nodes/block) -------
__global__ __launch_bounds__(256) void lin1_kernel(const float* __restrict__ x,
                                                   const float* __restrict__ W1){
    __shared__ float Ws[16*64];
    __shared__ float xs[4][16];
    int t = threadIdx.x;
    int nl = t >> 6, tc = t & 63;
    int n = blockIdx.x*4 + nl;
    for (int i = t; i < 1024; i += 256) Ws[i] = W1[i];
    if (t < 64) xs[t >> 4][t & 15] = x[blockIdx.x*64 + t];
    __syncthreads();
    float acc = 0.f;
#pragma unroll
    for (int k = 0; k < 16; k++) acc += xs[nl][k] * Ws[k*64 + tc];
    g_h1lin_h[n*64 + tc] = __float2half(acc);
    if (tc < 16){
        int h = tc & 7;
        const float* M = (tc < 8) ? g_M1s : g_M1d;
        float s = 0.f;
#pragma unroll
        for (int k = 0; k < 16; k++) s += xs[nl][k] * M[k*8 + h];
        if (tc < 8) g_as1[n*8 + h] = s;
        else        g_ad1[n*8 + h] = s;
    }
}

// ------- GAT1 aggregation: warp per node, fp16 gather, syncless ------------
__global__ __launch_bounds__(64) void agg1_kernel(const float* __restrict__ bias){
    int t = threadIdx.x;
    int wp = t >> 5, l = t & 31;
    int d = blockIdx.x*2 + wp;
    int g = l >> 2;                         // head for channels 2l, 2l+1
    int beg = d*CAP, end = beg + g_deg[d];
    float ad = g_ad1[d*8 + g];
    float ws0 = __expf(lrelu(g_as1[d*8 + g] + ad));     // self loop
    float2 h0 = __half22float2(*(const __half2*)(g_h1lin_h + d*64 + 2*l));
    float ax = ws0*h0.x, ay = ws0*h0.y;
    float dp = ws0;
    int i = beg;
    for (; i + 4 <= end; i += 4){
        int s0 = g_srcs[i], s1 = g_srcs[i+1], s2 = g_srcs[i+2], s3 = g_srcs[i+3];
        float w0 = __expf(lrelu(g_as1[s0*8 + g] + ad));
        float w1 = __expf(lrelu(g_as1[s1*8 + g] + ad));
        float w2 = __expf(lrelu(g_as1[s2*8 + g] + ad));
        float w3 = __expf(lrelu(g_as1[s3*8 + g] + ad));
        float2 v0 = __half22float2(*(const __half2*)(g_h1lin_h + s0*64 + 2*l));
        float2 v1 = __half22float2(*(const __half2*)(g_h1lin_h + s1*64 + 2*l));
        float2 v2 = __half22float2(*(const __half2*)(g_h1lin_h + s2*64 + 2*l));
        float2 v3 = __half22float2(*(const __half2*)(g_h1lin_h + s3*64 + 2*l));
        dp += w0 + w1 + w2 + w3;
        ax += w0*v0.x; ay += w0*v0.y;
        ax += w1*v1.x; ay += w1*v1.y;
        ax += w2*v2.x; ay += w2*v2.y;
        ax += w3*v3.x; ay += w3*v3.y;
    }
    for (; i < end; i++){
        int s = g_srcs[i];
        float we = __expf(lrelu(g_as1[s*8 + g] + ad));
        float2 v = __half22float2(*(const __half2*)(g_h1lin_h + s*64 + 2*l));
        dp += we;
        ax += we*v.x; ay += we*v.y;
    }
    float inv = 1.f / (dp + 1e-16f);
    float2 b2 = *(const float2*)(bias + 2*l);
    float h1a = fmaxf(ax*inv + b2.x, 0.f);
    float h1b = fmaxf(ay*inv + b2.y, 0.f);
    *(__half2*)(g_h1h + d*64 + 2*l) = __floats2half2_rn(h1a, h1b);
    // fused alpha2: as2[d,h] = h1[d,:] . Ms[:,h]  (pure warp shuffles)
#pragma unroll
    for (int h = 0; h < 8; h++){
        float vs = h1a*g_Ms[(2*l)*8 + h] + h1b*g_Ms[(2*l+1)*8 + h];
        float vd = h1a*g_Md[(2*l)*8 + h] + h1b*g_Md[(2*l+1)*8 + h];
#pragma unroll
        for (int off = 16; off; off >>= 1){
            vs += __shfl_down_sync(~0u, vs, off);
            vd += __shfl_down_sync(~0u, vd, off);
        }
        if (l == 0){
            g_as2[d*8 + h] = vs;
            g_ad2[d*8 + h] = vd;
        }
    }
}

// --------- layer 2 GEMM via wmma: h1h[8192,64] @ W2h[64,1024] -> fp16 ------
__global__ __launch_bounds__(256) void gemm2_kernel(){
    __shared__ float sc[8][16][16];
    int t = threadIdx.x, w = t >> 5, l = t & 31;
    int m0 = blockIdx.y * 16;
    int n0 = blockIdx.x * 128 + w * 16;
    wmma::fragment<wmma::matrix_a, 16, 16, 16, half, wmma::row_major> fa;
    wmma::fragment<wmma::matrix_b, 16, 16, 16, half, wmma::row_major> fb;
    wmma::fragment<wmma::accumulator, 16, 16, 16, float> fc;
    wmma::fill_fragment(fc, 0.f);
#pragma unroll
    for (int k = 0; k < 64; k += 16){
        wmma::load_matrix_sync(fa, g_h1h + m0*64 + k, 64);
        wmma::load_matrix_sync(fb, g_W2h + k*1024 + n0, 1024);
        wmma::mma_sync(fc, fa, fb, fc);
    }
    wmma::store_matrix_sync(&sc[w][0][0], fc, 16, wmma::mem_row_major);
    __syncwarp();
    // pack + store: lane l -> row l>>1, cols (l&1)*8 .. +7  (16B per lane)
    int r = l >> 1, c0 = (l & 1) * 8;
    const float* src = &sc[w][r][c0];
    h8 o;
    o.a = __floats2half2_rn(src[0], src[1]);
    o.b = __floats2half2_rn(src[2], src[3]);
    o.c = __floats2half2_rn(src[4], src[5]);
    o.d = __floats2half2_rn(src[6], src[7]);
    *(h8*)(g_h2lin_h + (size_t)(m0 + r)*1024 + n0 + c0) = o;
}

// ---------------- GAT2 aggregation (single-pass, fp16 gather) --------------
__global__ __launch_bounds__(256) void agg2_kernel(const float* __restrict__ bias){
    int d = blockIdx.x, t = threadIdx.x;
    int w = t >> 5, l = t & 31;
    __shared__ float adl[8], den_s[8];
    if (t < 8) adl[t] = g_ad2[d*8 + t];
    __syncthreads();
    int beg = d*CAP, end = beg + g_deg[d];
    float ad = adl[w];
    float ws0 = __expf(lrelu(g_as2[d*8 + w] + ad));     // self loop
    int cofs = t*4;
    float4 acc;
    {
        h4 v = *(const h4*)(g_h2lin_h + (size_t)d*1024 + cofs);
        float2 f0 = __half22float2(v.a), f1 = __half22float2(v.b);
        acc.x = ws0*f0.x; acc.y = ws0*f0.y; acc.z = ws0*f1.x; acc.w = ws0*f1.y;
    }
    float dp = ws0;
    int i = beg;
    for (; i + 4 <= end; i += 4){
        int s0 = g_srcs[i], s1 = g_srcs[i+1], s2 = g_srcs[i+2], s3 = g_srcs[i+3];
        float w0 = __expf(lrelu(g_as2[s0*8 + w] + ad));
        float w1 = __expf(lrelu(g_as2[s1*8 + w] + ad));
        float w2 = __expf(lrelu(g_as2[s2*8 + w] + ad));
        float w3 = __expf(lrelu(g_as2[s3*8 + w] + ad));
        h4 p0 = *(const h4*)(g_h2lin_h + (size_t)s0*1024 + cofs);
        h4 p1 = *(const h4*)(g_h2lin_h + (size_t)s1*1024 + cofs);
        h4 p2 = *(const h4*)(g_h2lin_h + (size_t)s2*1024 + cofs);
        h4 p3 = *(const h4*)(g_h2lin_h + (size_t)s3*1024 + cofs);
        dp += w0 + w1 + w2 + w3;
        float2 a0 = __half22float2(p0.a), b0 = __half22float2(p0.b);
        float2 a1 = __half22float2(p1.a), b1 = __half22float2(p1.b);
        float2 a2 = __half22float2(p2.a), b2 = __half22float2(p2.b);
        float2 a3 = __half22float2(p3.a), b3 = __half22float2(p3.b);
        acc.x += w0*a0.x; acc.y += w0*a0.y; acc.z += w0*b0.x; acc.w += w0*b0.y;
        acc.x += w1*a1.x; acc.y += w1*a1.y; acc.z += w1*b1.x; acc.w += w1*b1.y;
        acc.x += w2*a2.x; acc.y += w2*a2.y; acc.z += w2*b2.x; acc.w += w2*b2.y;
        acc.x += w3*a3.x; acc.y += w3*a3.y; acc.z += w3*b3.x; acc.w += w3*b3.y;
    }
    for (; i < end; i++){
        int s = g_srcs[i];
        float we = __expf(lrelu(g_as2[s*8 + w] + ad));
        h4 p = *(const h4*)(g_h2lin_h + (size_t)s*1024 + cofs);
        float2 a0 = __half22float2(p.a), b0 = __half22float2(p.b);
        dp += we;
        acc.x += we*a0.x; acc.y += we*a0.y; acc.z += we*b0.x; acc.w += we*b0.y;
    }
    if (l == 0) den_s[w] = dp + 1e-16f;
    __syncthreads();
    float inv = 1.f / den_s[w];
    float4 b4 = *(const float4*)(bias + cofs);
    h4 o;
    o.a = __floats2half2_rn(fmaxf(acc.x*inv + b4.x, 0.f), fmaxf(acc.y*inv + b4.y, 0.f));
    o.b = __floats2half2_rn(fmaxf(acc.z*inv + b4.z, 0.f), fmaxf(acc.w*inv + b4.w, 0.f));
    *(h4*)(g_h2h + (size_t)d*1024 + cofs) = o;
}

// ---------------- merged dueling heads GEMV (val 64 cols + adv 16 cols) ----
#define HK_SPAN 1024
#define HK_SUB  256
__global__ __launch_bounds__(256) void head_kernel(const float* __restrict__ Wval,
                                                   const float* __restrict__ Wadv){
    __shared__ __align__(16) float Hs[2][HK_SUB][8];   // 16KB, [buf][k][batch]
    int t = threadIdx.x;
    int w = t >> 5, l = t & 31;
    int kbase = blockIdx.x * HK_SPAN;
    int c4v = t & 15, jv = t >> 4;
    int c4a = t & 3,  ja = t >> 2;
    const float4* Wv4 = (const float4*)Wval;
    const float4* Wa4 = (const float4*)Wadv;

    ull vacc[4][4];                 // [batch-pair][col]
#pragma unroll
    for (int p = 0; p < 4; p++)
#pragma unroll
        for (int c = 0; c < 4; c++) vacc[p][c] = 0ull;
    float4 aa[8];
#pragma unroll
    for (int b = 0; b < 8; b++) aa[b] = make_float4(0.f,0.f,0.f,0.f);

    // preload tile 0 (transposed: Hs[k][b])
#pragma unroll
    for (int q = 0; q < 8; q++)
        Hs[0][t][q] = __half2float(g_h2h[(size_t)q*1048576 + kbase + t]);
    __syncthreads();

    for (int st = 0; st < HK_SPAN/HK_SUB; st++){
        int cur = st & 1;
        float rn[8];
        if (st < HK_SPAN/HK_SUB - 1){
#pragma unroll
            for (int q = 0; q < 8; q++)
                rn[q] = __half2float(g_h2h[(size_t)q*1048576 + kbase + (st+1)*HK_SUB + t]);
        }
        int k0g = kbase + st*HK_SUB;
        // ---- val: 64 cols, f32x2 over batch pairs ----
#pragma unroll 4
        for (int ii = 0; ii < HK_SUB/16; ii++){
            int k = jv + 16*ii;
            float4 w4 = __ldcs(&Wv4[(size_t)(k0g + k)*16 + c4v]);
            ull h01 = *(const ull*)&Hs[cur][k][0];
            ull h23 = *(const ull*)&Hs[cur][k][2];
            ull h45 = *(const ull*)&Hs[cur][k][4];
            ull h67 = *(const ull*)&Hs[cur][k][6];
            ull wx = pack2(w4.x, w4.x), wy = pack2(w4.y, w4.y);
            ull wz = pack2(w4.z, w4.z), ww = pack2(w4.w, w4.w);
            fma2(vacc[0][0], h01, wx); fma2(vacc[1][0], h23, wx);
            fma2(vacc[2][0], h45, wx); fma2(vacc[3][0], h67, wx);
            fma2(vacc[0][1], h01, wy); fma2(vacc[1][1], h23, wy);
            fma2(vacc[2][1], h45, wy); fma2(vacc[3][1], h67, wy);
            fma2(vacc[0][2], h01, wz); fma2(vacc[1][2], h23, wz);
            fma2(vacc[2][2], h45, wz); fma2(vacc[3][2], h67, wz);
            fma2(vacc[0][3], h01, ww); fma2(vacc[1][3], h23, ww);
            fma2(vacc[2][3], h45, ww); fma2(vacc[3][3], h67, ww);
        }
        // ---- adv: 16 cols ----
#pragma unroll
        for (int ii = 0; ii < HK_SUB/64; ii++){
            int k = ja + 64*ii;
            float4 w4 = __ldcs(&Wa4[(size_t)(k0g + k)*4 + c4a]);
#pragma unroll
            for (int b = 0; b < 8; b++){
                float h = Hs[cur][k][b];
                aa[b].x += h*w4.x; aa[b].y += h*w4.y;
                aa[b].z += h*w4.z; aa[b].w += h*w4.w;
            }
        }
        __syncthreads();
        if (st < HK_SPAN/HK_SUB - 1){
#pragma unroll
            for (int q = 0; q < 8; q++) Hs[1-cur][t][q] = rn[q];
            __syncthreads();
        }
    }

    // unpack val accumulators into per-batch float4
    float4 va[8];
#pragma unroll
    for (int p = 0; p < 4; p++){
        float lo, hi;
        unpack2(vacc[p][0], lo, hi); va[2*p].x = lo; va[2*p+1].x = hi;
        unpack2(vacc[p][1], lo, hi); va[2*p].y = lo; va[2*p+1].y = hi;
        unpack2(vacc[p][2], lo, hi); va[2*p].z = lo; va[2*p+1].z = hi;
        unpack2(vacc[p][3], lo, hi); va[2*p].w = lo; va[2*p+1].w = hi;
    }

    float4* red4 = (float4*)&Hs[0][0][0];   // reuse (all threads past final barrier)
    // ---- val reduce: jv pairs (lane offset 16), then across warps ----
#pragma unroll
    for (int b = 0; b < 8; b++) shfl_add(va[b], 16);
    if (l < 16){
#pragma unroll
        for (int b = 0; b < 8; b++) red4[(w*16 + l)*8 + b] = va[b];
    }
    __syncthreads();
    if (t < 128){
        int cc = t & 15, b = t >> 4;
        float4 s = make_float4(0.f,0.f,0.f,0.f);
#pragma unroll
        for (int ww = 0; ww < 8; ww++){
            float4 v = red4[(ww*16 + cc)*8 + b];
            s.x += v.x; s.y += v.y; s.z += v.z; s.w += v.w;
        }
        float* dst = g_valacc + b*64 + cc*4;
        atomicAdd(dst+0, s.x); atomicAdd(dst+1, s.y);
        atomicAdd(dst+2, s.z); atomicAdd(dst+3, s.w);
    }
    __syncthreads();
    // ---- adv reduce: within warp across ja (4,8,16), then warps ----
#pragma unroll
    for (int b = 0; b < 8; b++){
        shfl_add(aa[b], 4); shfl_add(aa[b], 8); shfl_add(aa[b], 16);
    }
    if (l < 4){
#pragma unroll
        for (int b = 0; b < 8; b++) red4[(w*4 + l)*8 + b] = aa[b];
    }
    __syncthreads();
    if (t < 32){
        int cc = t & 3, b = t >> 2;
        float4 s = make_float4(0.f,0.f,0.f,0.f);
#pragma unroll
        for (int ww = 0; ww < 8; ww++){
            float4 v = red4[(ww*4 + cc)*8 + b];
            s.x += v.x; s.y += v.y; s.z += v.z; s.w += v.w;
        }
        float* dst = g_advacc + b*16 + cc*4;
        atomicAdd(dst+0, s.x); atomicAdd(dst+1, s.y);
        atomicAdd(dst+2, s.z); atomicAdd(dst+3, s.w);
    }
}

// ---------- finalize: val MLP + dueling combine + re-zero accumulators -----
__global__ __launch_bounds__(512) void final_kernel(const float* __restrict__ adv_b,
                                                    const float* __restrict__ v1b,
                                                    const float* __restrict__ v2w,
                                                    const float* __restrict__ v2b,
                                                    const float* __restrict__ v3w,
                                                    const float* __restrict__ v3b,
                                                    float* __restrict__ out){
    int t = threadIdx.x;
    __shared__ float v1[512], v2s[512], vS[8], advs[128];
    v1[t] = fmaxf(g_valacc[t] + v1b[t & 63], 0.f);
    g_valacc[t] = 0.f;                                  // re-zero for next call
    if (t < 128){
        advs[t] = fmaxf(g_advacc[t] + adv_b[t & 15], 0.f);
        g_advacc[t] = 0.f;
    }
#pragma unroll
    for (int i = t; i < NNODES; i += 512) g_deg[i] = 0; // re-zero for next call
    __syncthreads();
    {
        int b = t >> 6, c = t & 63;
        float s2 = v2b[c];
        for (int k = 0; k < 64; k++) s2 += v1[b*64 + k] * v2w[k*64 + c];
        v2s[t] = fmaxf(s2, 0.f);
    }
    __syncthreads();
    if (t < 8){
        float s3 = v3b[0];
        for (int k = 0; k < 64; k++) s3 += v2s[t*64 + k] * v3w[k];
        vS[t] = s3;
    }
    __syncthreads();
    if (t < 128){
        int base = t & ~3;
        float mean = 0.25f*(advs[base] + advs[base+1] + advs[base+2] + advs[base+3]);
        out[t] = vS[t >> 4] + advs[t] - mean;
    }
}

// ---------------- launch ----------------
extern "C" void kernel_launch(void* const* d_in, const int* in_sizes, int n_in,
                              void* d_out, int out_size){
    const float* x      = (const float*)d_in[0];
    const void*  edge   = d_in[1];
    const float* W1     = (const float*)d_in[2];
    const float* a_src1 = (const float*)d_in[3];
    const float* a_dst1 = (const float*)d_in[4];
    const float* b1     = (const float*)d_in[5];
    const float* W2     = (const float*)d_in[6];
    const float* a_src2 = (const float*)d_in[7];
    const float* a_dst2 = (const float*)d_in[8];
    const float* b2     = (const float*)d_in[9];
    const float* adv_w  = (const float*)d_in[10];
    const float* adv_b  = (const float*)d_in[11];
    const float* val1_w = (const float*)d_in[12];
    const float* val1_b = (const float*)d_in[13];
    const float* val2_w = (const float*)d_in[14];
    const float* val2_b = (const float*)d_in[15];
    const float* val3_w = (const float*)d_in[16];
    const float* val3_b = (const float*)d_in[17];
    float* out = (float*)d_out;

    prep_kernel<<<74, 512>>>((const int*)edge, W1, a_src1, a_dst1, W2, a_src2, a_dst2);
    scatter_kernel<<<NEDGES/256, 256>>>(edge);          // one-pass bucket CSR
    lin1_kernel<<<NNODES/4, 256>>>(x, W1);

    agg1_kernel<<<NNODES/2, 64>>>(b1);
    gemm2_kernel<<<dim3(8, 512), 256>>>();
    agg2_kernel<<<NNODES, 256>>>(b2);

    head_kernel<<<1024, 256>>>(val1_w, adv_w);
    final_kernel<<<1, 512>>>(adv_b, val1_b, val2_w, val2_b, val3_w, val3_b, out);
}